// round 5
// baseline (speedup 1.0000x reference)
#include <cuda_runtime.h>
#include <stdint.h>
#include <math_constants.h>

// WinnerTakeAll: per-row top-k (k=1000), rows of 20000 fp32, 4096 rows.
// One CTA/row. Sample-bracketed exact selection with FLOAT-compare hot loop:
//  1. Sample 2048 elems, histogram on 11-bit key bins, pick bracket bins at
//     sample ranks 52 / 180; convert bin edges to float thresholds hi_f/lo_f.
//  2. ONE full-row pass (pure FSETP/FSEL): out = v>=hi_f ? v : 0, count above,
//     ballot-aggregated append of candidates in [lo_f, hi_f) to SMEM.
//  3. Verify c_above < k <= c_above+ccount & no overflow; else exact SLOW PATH.
//  4. Exact k-th key via 11/11/10 radix over ~1.5K SMEM candidates; scatter fixup.

#define DCOLS    20000
#define KKEEP    1000u
#define NT       512
#define NBINS    2048
#define CAND_MAX 4096
#define R_HI     52u
#define R_LO     180u

struct Smem {
    uint32_t hist[NBINS];        // 8 KB
    uint32_t cand[CAND_MAX];     // 16 KB
    uint16_t cidx[CAND_MAX];     // 8 KB
    uint32_t cand_count;
    uint32_t c_above;
    uint32_t bHi, bLo, scr0, scr1;
    uint32_t bA, kkA;
    uint32_t bB, kkB;
    uint32_t bC, kkC, cntC;
};

__device__ __forceinline__ uint32_t f2u(float f) {
    uint32_t b = __float_as_uint(f);
    return b ^ ((b & 0x80000000u) ? 0xFFFFFFFFu : 0x80000000u);
}
__device__ __forceinline__ float u2f(uint32_t u) {
    uint32_t b = (u & 0x80000000u) ? (u ^ 0x80000000u) : (u ^ 0xFFFFFFFFu);
    return __uint_as_float(b);
}

// Warp-aggregated histogram add (ALL 32 lanes participate).
__device__ __forceinline__ void hist_add(uint32_t* hist, uint32_t bin, bool valid) {
    uint32_t key = valid ? bin : 0xFFFFFFFFu;
    unsigned m = __match_any_sync(0xFFFFFFFFu, key);
    int leader = __ffs(m) - 1;
    if (valid && (int)(threadIdx.x & 31) == leader)
        atomicAdd(&hist[bin], (uint32_t)__popc(m));
}

// Scan histogram from TOP bin down for the kk-th largest. Warp 0 only.
__device__ __forceinline__ void select_from_top(const uint32_t* hist, int nbins, uint32_t kk,
                                                uint32_t* out_bin, uint32_t* out_kk, uint32_t* out_cnt) {
    int lane = threadIdx.x & 31;
    uint32_t cum = 0;
    for (int base = nbins - 32; base >= 0; base -= 32) {
        uint32_t v = hist[base + 31 - lane];
        uint32_t incl = v;
        #pragma unroll
        for (int off = 1; off < 32; off <<= 1) {
            uint32_t t = __shfl_up_sync(0xFFFFFFFFu, incl, off);
            if (lane >= off) incl += t;
        }
        uint32_t total = __shfl_sync(0xFFFFFFFFu, incl, 31);
        unsigned hm = __ballot_sync(0xFFFFFFFFu, cum + incl >= kk);
        if (hm) {
            int l = __ffs(hm) - 1;
            if (lane == l) {
                *out_bin = (uint32_t)(base + 31 - l);
                *out_kk  = kk - cum - (incl - v);
                *out_cnt = v;
            }
            return;
        }
        cum += total;
    }
    if (lane == 0) { *out_bin = 0; *out_kk = 1; *out_cnt = 1; }
}

extern "C" __global__ void __launch_bounds__(NT, 4)
wta_kernel(const float* __restrict__ in, float* __restrict__ out, int rows) {
    __shared__ Smem s;

    const int row = blockIdx.x;
    if (row >= rows) return;
    const int tid = threadIdx.x;
    const int lane = tid & 31;

    const float4* rowp = reinterpret_cast<const float4*>(in + (size_t)row * DCOLS);
    const float*  rowf = in + (size_t)row * DCOLS;
    float4* outp = reinterpret_cast<float4*>(out + (size_t)row * DCOLS);
    float*  outf = out + (size_t)row * DCOLS;
    const int nvec = DCOLS / 4;                 // 5000
    const int niter = (nvec + NT - 1) / NT;     // 10

    // ---- init ----
    {
        uint4* h4 = reinterpret_cast<uint4*>(s.hist);
        h4[tid] = make_uint4(0, 0, 0, 0);
    }
    if (tid == 0) { s.cand_count = 0; s.c_above = 0; }
    __syncthreads();

    // ---- step 1: sample 2048 elements, histogram key bins ----
    {
        float4 v = rowp[tid];
        hist_add(s.hist, f2u(v.x) >> 21, true);
        hist_add(s.hist, f2u(v.y) >> 21, true);
        hist_add(s.hist, f2u(v.z) >> 21, true);
        hist_add(s.hist, f2u(v.w) >> 21, true);
    }
    __syncthreads();

    if (tid < 32) {
        select_from_top(s.hist, NBINS, R_HI, &s.bHi, &s.scr0, &s.scr1);
        __syncwarp();
        select_from_top(s.hist, NBINS, R_LO, &s.bLo, &s.scr0, &s.scr1);
    }
    __syncthreads();

    // float thresholds from bin edges (order-isomorphic to key compare, non-NaN)
    float hi_f, lo_f;
    {
        uint64_t he = ((uint64_t)s.bHi + 1ull) << 21;
        hi_f = (he > 0xFFFFFFFFull) ? CUDART_INF_F : u2f((uint32_t)he);
        if (isnan(hi_f)) hi_f = CUDART_INF_F;
        lo_f = u2f(s.bLo << 21);
        if (isnan(lo_f)) lo_f = -CUDART_INF_F;
    }

    // clear hist for the candidate radix passes
    {
        uint4* h4 = reinterpret_cast<uint4*>(s.hist);
        h4[tid] = make_uint4(0, 0, 0, 0);
    }

    // ---- step 2: single full-row pass (float compares only) ----
    uint32_t my_above = 0;
    #pragma unroll 2
    for (int it = 0; it < niter; it++) {
        int i = tid + it * NT;
        bool valid = i < nvec;
        float4 v = make_float4(0.f, 0.f, 0.f, 0.f);
        if (valid) v = rowp[i];
        float vv[4] = { v.x, v.y, v.z, v.w };
        float ov[4];
        bool  cd[4];
        #pragma unroll
        for (int j = 0; j < 4; j++) {
            bool above = valid && (vv[j] >= hi_f);
            ov[j] = above ? vv[j] : 0.0f;
            my_above += above;
            cd[j] = valid && !above && (vv[j] >= lo_f);
        }
        // ballot-aggregated candidate append (one atomic per warp per iter)
        unsigned m0 = __ballot_sync(0xFFFFFFFFu, cd[0]);
        unsigned m1 = __ballot_sync(0xFFFFFFFFu, cd[1]);
        unsigned m2 = __ballot_sync(0xFFFFFFFFu, cd[2]);
        unsigned m3 = __ballot_sync(0xFFFFFFFFu, cd[3]);
        unsigned c0 = __popc(m0), c1 = __popc(m1), c2 = __popc(m2), c3 = __popc(m3);
        unsigned tot = c0 + c1 + c2 + c3;
        if (tot) {
            uint32_t base = 0;
            if (lane == 0) base = atomicAdd(&s.cand_count, tot);
            base = __shfl_sync(0xFFFFFFFFu, base, 0);
            unsigned lt = (1u << lane) - 1u;
            uint32_t off0 = base;
            uint32_t off1 = off0 + c0;
            uint32_t off2 = off1 + c1;
            uint32_t off3 = off2 + c2;
            uint32_t offs[4] = { off0 + __popc(m0 & lt), off1 + __popc(m1 & lt),
                                 off2 + __popc(m2 & lt), off3 + __popc(m3 & lt) };
            #pragma unroll
            for (int j = 0; j < 4; j++) {
                if (cd[j] && offs[j] < CAND_MAX) {
                    s.cand[offs[j]] = f2u(vv[j]);
                    s.cidx[offs[j]] = (uint16_t)(i * 4 + j);
                }
            }
        }
        if (valid) {
            float4 o; o.x = ov[0]; o.y = ov[1]; o.z = ov[2]; o.w = ov[3];
            outp[i] = o;
        }
    }
    #pragma unroll
    for (int off = 16; off > 0; off >>= 1)
        my_above += __shfl_down_sync(0xFFFFFFFFu, my_above, off);
    if (lane == 0 && my_above) atomicAdd(&s.c_above, my_above);
    __syncthreads();

    uint32_t c_above = s.c_above;
    uint32_t ccount  = s.cand_count;
    bool fast = (c_above < KKEEP) && (c_above + ccount >= KKEEP) && (ccount <= CAND_MAX);

    if (!fast) {
        // ================= SLOW PATH (rare; rewrites entire row) =================
        __syncthreads();
        {
            uint4* h4 = reinterpret_cast<uint4*>(s.hist);
            h4[tid] = make_uint4(0, 0, 0, 0);
        }
        if (tid == 0) s.cand_count = 0;
        __syncthreads();

        #pragma unroll 1
        for (int it = 0; it < niter; it++) {
            int i = tid + it * NT;
            bool valid = i < nvec;
            uint32_t u0 = 0, u1 = 0, u2 = 0, u3 = 0;
            if (valid) {
                float4 v = rowp[i];
                u0 = f2u(v.x); u1 = f2u(v.y); u2 = f2u(v.z); u3 = f2u(v.w);
            }
            hist_add(s.hist, u0 >> 21, valid);
            hist_add(s.hist, u1 >> 21, valid);
            hist_add(s.hist, u2 >> 21, valid);
            hist_add(s.hist, u3 >> 21, valid);
        }
        __syncthreads();
        if (tid < 32) select_from_top(s.hist, NBINS, KKEEP, &s.bA, &s.kkA, &s.cntC);
        __syncthreads();
        const uint32_t b1 = s.bA;
        const uint32_t kk1 = s.kkA;

        #pragma unroll 1
        for (int it = 0; it < niter; it++) {
            int i = tid + it * NT;
            if (i >= nvec) break;
            float4 v = rowp[i];
            float vv[4] = { v.x, v.y, v.z, v.w };
            uint32_t uu[4] = { f2u(v.x), f2u(v.y), f2u(v.z), f2u(v.w) };
            float ov[4];
            #pragma unroll
            for (int j = 0; j < 4; j++) {
                uint32_t bin = uu[j] >> 21;
                ov[j] = (bin > b1) ? vv[j] : 0.0f;
                if (bin == b1) {
                    uint32_t pos = atomicAdd(&s.cand_count, 1u);
                    if (pos < CAND_MAX) { s.cand[pos] = uu[j]; s.cidx[pos] = (uint16_t)(i * 4 + j); }
                }
            }
            float4 o; o.x = ov[0]; o.y = ov[1]; o.z = ov[2]; o.w = ov[3];
            outp[i] = o;
        }
        __syncthreads();

        const uint32_t cc2 = s.cand_count;
        const bool use_cand = (cc2 <= CAND_MAX);
        const int nitems = use_cand ? (int)cc2 : DCOLS;
        const int niterB = (nitems + NT - 1) / NT;

        {
            uint4* h4 = reinterpret_cast<uint4*>(s.hist);
            h4[tid] = make_uint4(0, 0, 0, 0);
        }
        __syncthreads();
        #pragma unroll 1
        for (int it = 0; it < niterB; it++) {
            int i = tid + it * NT;
            bool valid = i < nitems;
            uint32_t u = 0;
            if (valid) u = use_cand ? s.cand[i] : f2u(rowf[i]);
            valid = valid && (use_cand || ((u >> 21) == b1));
            hist_add(s.hist, (u >> 10) & 0x7FFu, valid);
        }
        __syncthreads();
        if (tid < 32) select_from_top(s.hist, NBINS, kk1, &s.bB, &s.kkB, &s.cntC);
        __syncthreads();
        const uint32_t b2 = s.bB;
        const uint32_t kk2 = s.kkB;
        const uint32_t pref22 = (b1 << 11) | b2;

        for (int i = tid; i < 1024; i += NT) s.hist[i] = 0;
        __syncthreads();
        #pragma unroll 1
        for (int it = 0; it < niterB; it++) {
            int i = tid + it * NT;
            bool valid = i < nitems;
            uint32_t u = 0;
            if (valid) u = use_cand ? s.cand[i] : f2u(rowf[i]);
            valid = valid && ((u >> 10) == pref22);
            hist_add(s.hist, u & 0x3FFu, valid);
        }
        __syncthreads();
        if (tid < 32) select_from_top(s.hist, 1024, kk2, &s.bC, &s.kkC, &s.cntC);
        __syncthreads();

        const uint32_t u_t = (b1 << 21) | (b2 << 10) | s.bC;
        const uint32_t A = s.kkC;
        const uint32_t T = s.cntC;
        const bool keep_all_ties = (A == T);

        if (use_cand) {
            for (uint32_t q = tid; q < cc2; q += NT) {
                uint32_t u = s.cand[q];
                bool keep = (u > u_t);
                if (!keep && u == u_t) {
                    if (keep_all_ties) keep = true;
                    else {
                        uint32_t rank = 0;
                        for (uint32_t p = 0; p < cc2; p++)
                            rank += (s.cand[p] == u_t && s.cidx[p] < s.cidx[q]);
                        keep = (rank < A);
                    }
                }
                if (keep) outf[s.cidx[q]] = u2f(u);
            }
        } else {
            for (int i = tid; i < DCOLS; i += NT) {
                uint32_t u = f2u(rowf[i]);
                if ((u >> 21) != b1) continue;
                bool keep = (u > u_t);
                if (!keep && u == u_t) {
                    if (keep_all_ties) keep = true;
                    else {
                        uint32_t rank = 0;
                        for (int q = 0; q < i; q++) rank += (f2u(rowf[q]) == u_t);
                        keep = (rank < A);
                    }
                }
                if (keep) outf[i] = u2f(u);
            }
        }
        return;
    }

    // ================= FAST PATH: exact select over SMEM candidates =================
    const uint32_t kk = KKEEP - c_above;
    const int niterC = ((int)ccount + NT - 1) / NT;

    #pragma unroll 1
    for (int it = 0; it < niterC; it++) {
        int i = tid + it * NT;
        bool valid = i < (int)ccount;
        uint32_t u = valid ? s.cand[i] : 0;
        hist_add(s.hist, u >> 21, valid);
    }
    __syncthreads();
    if (tid < 32) select_from_top(s.hist, NBINS, kk, &s.bA, &s.kkA, &s.cntC);
    __syncthreads();
    const uint32_t b1 = s.bA;
    const uint32_t kk1 = s.kkA;

    {
        uint4* h4 = reinterpret_cast<uint4*>(s.hist);
        h4[tid] = make_uint4(0, 0, 0, 0);
    }
    __syncthreads();
    #pragma unroll 1
    for (int it = 0; it < niterC; it++) {
        int i = tid + it * NT;
        bool valid = i < (int)ccount;
        uint32_t u = valid ? s.cand[i] : 0;
        valid = valid && ((u >> 21) == b1);
        hist_add(s.hist, (u >> 10) & 0x7FFu, valid);
    }
    __syncthreads();
    if (tid < 32) select_from_top(s.hist, NBINS, kk1, &s.bB, &s.kkB, &s.cntC);
    __syncthreads();
    const uint32_t b2 = s.bB;
    const uint32_t kk2 = s.kkB;
    const uint32_t pref22 = (b1 << 11) | b2;

    for (int i = tid; i < 1024; i += NT) s.hist[i] = 0;
    __syncthreads();
    #pragma unroll 1
    for (int it = 0; it < niterC; it++) {
        int i = tid + it * NT;
        bool valid = i < (int)ccount;
        uint32_t u = valid ? s.cand[i] : 0;
        valid = valid && ((u >> 10) == pref22);
        hist_add(s.hist, u & 0x3FFu, valid);
    }
    __syncthreads();
    if (tid < 32) select_from_top(s.hist, 1024, kk2, &s.bC, &s.kkC, &s.cntC);
    __syncthreads();

    const uint32_t u_t = (b1 << 21) | (b2 << 10) | s.bC;
    const uint32_t A = s.kkC;
    const uint32_t T = s.cntC;
    const bool keep_all_ties = (A == T);

    for (uint32_t q = tid; q < ccount; q += NT) {
        uint32_t u = s.cand[q];
        bool keep = (u > u_t);
        if (!keep && u == u_t) {
            if (keep_all_ties) keep = true;
            else {
                uint32_t rank = 0;
                for (uint32_t p = 0; p < ccount; p++)
                    rank += (s.cand[p] == u_t && s.cidx[p] < s.cidx[q]);
                keep = (rank < A);
            }
        }
        if (keep) outf[s.cidx[q]] = u2f(u);
    }
}

extern "C" void kernel_launch(void* const* d_in, const int* in_sizes, int n_in,
                              void* d_out, int out_size) {
    const float* in = (const float*)d_in[0];
    float* out = (float*)d_out;
    int rows = in_sizes[0] / DCOLS;   // 4096
    wta_kernel<<<rows, NT>>>(in, out, rows);
}

// round 6
// speedup vs baseline: 1.0763x; 1.0763x over previous
#include <cuda_runtime.h>
#include <stdint.h>
#include <math_constants.h>

// WinnerTakeAll: per-row top-k (k=1000), rows of 20000 fp32, 4096 rows.
// One CTA/row. Single sampled threshold t_lo (bin edge, ~1650 candidates):
//  hot loop = FSETP + FSEL + predicated STS.U16 of index into PER-THREAD
//  private SMEM slots (no ballots/atomics/match). Output written speculatively
//  (v if v>=t_lo else 0). Tail: compact candidates, exact 11/11/10 radix
//  select of k-th key, zero the losers. Any statistical violation -> exact
//  slow path (full radix, rewrites row).

#define DCOLS    20000
#define KKEEP    1000u
#define NT       512
#define NBINS    2048
#define SLOTS    16
#define CAND_CAP 3072
#define R_LO     147u     // sample rank (of 2048) for the threshold bin

struct Smem {
    uint32_t hist[NBINS];          // 8 KB
    uint32_t cand[CAND_CAP];       // 12 KB
    uint16_t cidx[CAND_CAP];       // 6 KB
    uint16_t sidx[NT * SLOTS];     // 16 KB  per-thread candidate index slots
    uint32_t wsum[16], woff[16];
    uint32_t cand_count;
    uint32_t overflow;
    uint32_t bLo, scr0, scr1;
    uint32_t bA, kkA;
    uint32_t bB, kkB;
    uint32_t bC, kkC, cntC;
};

__device__ __forceinline__ uint32_t f2u(float f) {
    uint32_t b = __float_as_uint(f);
    return b ^ ((b & 0x80000000u) ? 0xFFFFFFFFu : 0x80000000u);
}
__device__ __forceinline__ float u2f(uint32_t u) {
    uint32_t b = (u & 0x80000000u) ? (u ^ 0x80000000u) : (u ^ 0xFFFFFFFFu);
    return __uint_as_float(b);
}

// Warp-aggregated histogram add (ALL 32 lanes participate).
__device__ __forceinline__ void hist_add(uint32_t* hist, uint32_t bin, bool valid) {
    uint32_t key = valid ? bin : 0xFFFFFFFFu;
    unsigned m = __match_any_sync(0xFFFFFFFFu, key);
    int leader = __ffs(m) - 1;
    if (valid && (int)(threadIdx.x & 31) == leader)
        atomicAdd(&hist[bin], (uint32_t)__popc(m));
}

// Scan histogram from TOP bin down for the kk-th largest. Warp 0 only.
__device__ __forceinline__ void select_from_top(const uint32_t* hist, int nbins, uint32_t kk,
                                                uint32_t* out_bin, uint32_t* out_kk, uint32_t* out_cnt) {
    int lane = threadIdx.x & 31;
    uint32_t cum = 0;
    for (int base = nbins - 32; base >= 0; base -= 32) {
        uint32_t v = hist[base + 31 - lane];
        uint32_t incl = v;
        #pragma unroll
        for (int off = 1; off < 32; off <<= 1) {
            uint32_t t = __shfl_up_sync(0xFFFFFFFFu, incl, off);
            if (lane >= off) incl += t;
        }
        uint32_t total = __shfl_sync(0xFFFFFFFFu, incl, 31);
        unsigned hm = __ballot_sync(0xFFFFFFFFu, cum + incl >= kk);
        if (hm) {
            int l = __ffs(hm) - 1;
            if (lane == l) {
                *out_bin = (uint32_t)(base + 31 - l);
                *out_kk  = kk - cum - (incl - v);
                *out_cnt = v;
            }
            return;
        }
        cum += total;
    }
    if (lane == 0) { *out_bin = 0; *out_kk = 1; *out_cnt = 1; }
}

extern "C" __global__ void __launch_bounds__(NT, 4)
wta_kernel(const float* __restrict__ in, float* __restrict__ out, int rows) {
    __shared__ Smem s;

    const int row = blockIdx.x;
    if (row >= rows) return;
    const int tid = threadIdx.x;
    const int lane = tid & 31;
    const int wid = tid >> 5;

    const float4* rowp = reinterpret_cast<const float4*>(in + (size_t)row * DCOLS);
    const float*  rowf = in + (size_t)row * DCOLS;
    float4* outp = reinterpret_cast<float4*>(out + (size_t)row * DCOLS);
    float*  outf = out + (size_t)row * DCOLS;
    const int nvec = DCOLS / 4;                 // 5000
    const int niter = (nvec + NT - 1) / NT;     // 10

    // ---- init ----
    {
        uint4* h4 = reinterpret_cast<uint4*>(s.hist);
        h4[tid] = make_uint4(0, 0, 0, 0);
    }
    if (tid == 0) { s.cand_count = 0; s.overflow = 0; }
    __syncthreads();

    // ---- step 1: sample 2048 elements, histogram 11-bit key bins ----
    {
        float4 v = rowp[tid];
        hist_add(s.hist, f2u(v.x) >> 21, true);
        hist_add(s.hist, f2u(v.y) >> 21, true);
        hist_add(s.hist, f2u(v.z) >> 21, true);
        hist_add(s.hist, f2u(v.w) >> 21, true);
    }
    __syncthreads();

    if (tid < 32) select_from_top(s.hist, NBINS, R_LO, &s.bLo, &s.scr0, &s.scr1);
    __syncthreads();

    float t_lo = u2f(s.bLo << 21);
    if (isnan(t_lo)) t_lo = -CUDART_INF_F;

    // clear hist for the candidate radix passes
    {
        uint4* h4 = reinterpret_cast<uint4*>(s.hist);
        h4[tid] = make_uint4(0, 0, 0, 0);
    }

    // ---- step 2: single full-row pass (lean: no cross-lane ops) ----
    uint32_t nloc = 0;
    const uint32_t slotbase = (uint32_t)tid * SLOTS;
    #pragma unroll
    for (int it = 0; it < 10; it++) {
        int i = tid + it * NT;
        bool valid = i < nvec;
        float4 v = make_float4(-CUDART_INF_F, -CUDART_INF_F, -CUDART_INF_F, -CUDART_INF_F);
        if (valid) v = rowp[i];
        float vv[4] = { v.x, v.y, v.z, v.w };
        float ov[4];
        #pragma unroll
        for (int j = 0; j < 4; j++) {
            bool c = vv[j] >= t_lo;        // padded lanes are -inf -> false
            ov[j] = c ? vv[j] : 0.0f;
            if (c) {
                if (nloc < SLOTS) s.sidx[slotbase + nloc] = (uint16_t)(i * 4 + j);
                nloc++;
            }
        }
        if (valid) {
            float4 o; o.x = ov[0]; o.y = ov[1]; o.z = ov[2]; o.w = ov[3];
            outp[i] = o;
        }
    }
    uint32_t nstore = nloc < SLOTS ? nloc : SLOTS;
    if (nloc > SLOTS) s.overflow = 1;

    // ---- block scan of per-thread counts -> compaction offsets ----
    uint32_t incl = nstore;
    #pragma unroll
    for (int off = 1; off < 32; off <<= 1) {
        uint32_t t = __shfl_up_sync(0xFFFFFFFFu, incl, off);
        if (lane >= off) incl += t;
    }
    if (lane == 31) s.wsum[wid] = incl;
    __syncthreads();
    if (tid < 16) {
        uint32_t v = s.wsum[tid];
        uint32_t inc2 = v;
        #pragma unroll
        for (int off = 1; off < 16; off <<= 1) {
            uint32_t t = __shfl_up_sync(0x0000FFFFu, inc2, off);
            if (tid >= off) inc2 += t;
        }
        s.woff[tid] = inc2 - v;
        if (tid == 15) s.cand_count = inc2;
    }
    __syncthreads();

    // ---- gather candidates into compact arrays (values from L2) ----
    {
        uint32_t myoff = s.woff[wid] + (incl - nstore);
        for (uint32_t n = 0; n < nstore; n++) {
            uint32_t pos = myoff + n;
            if (pos < CAND_CAP) {
                uint16_t idx = s.sidx[slotbase + n];
                s.cand[pos] = f2u(rowf[idx]);
                s.cidx[pos] = idx;
            }
        }
    }
    __syncthreads();

    const uint32_t ccount = s.cand_count;
    bool fast = (!s.overflow) && (ccount >= KKEEP) && (ccount <= CAND_CAP);

    if (!fast) {
        // ================= SLOW PATH (rare; rewrites entire row) =================
        __syncthreads();
        {
            uint4* h4 = reinterpret_cast<uint4*>(s.hist);
            h4[tid] = make_uint4(0, 0, 0, 0);
        }
        if (tid == 0) s.cand_count = 0;
        __syncthreads();

        #pragma unroll 1
        for (int it = 0; it < niter; it++) {
            int i = tid + it * NT;
            bool valid = i < nvec;
            uint32_t u0 = 0, u1 = 0, u2 = 0, u3 = 0;
            if (valid) {
                float4 v = rowp[i];
                u0 = f2u(v.x); u1 = f2u(v.y); u2 = f2u(v.z); u3 = f2u(v.w);
            }
            hist_add(s.hist, u0 >> 21, valid);
            hist_add(s.hist, u1 >> 21, valid);
            hist_add(s.hist, u2 >> 21, valid);
            hist_add(s.hist, u3 >> 21, valid);
        }
        __syncthreads();
        if (tid < 32) select_from_top(s.hist, NBINS, KKEEP, &s.bA, &s.kkA, &s.cntC);
        __syncthreads();
        const uint32_t b1 = s.bA;
        const uint32_t kk1 = s.kkA;

        #pragma unroll 1
        for (int it = 0; it < niter; it++) {
            int i = tid + it * NT;
            if (i >= nvec) break;
            float4 v = rowp[i];
            float vv[4] = { v.x, v.y, v.z, v.w };
            uint32_t uu[4] = { f2u(v.x), f2u(v.y), f2u(v.z), f2u(v.w) };
            float ov[4];
            #pragma unroll
            for (int j = 0; j < 4; j++) {
                uint32_t bin = uu[j] >> 21;
                ov[j] = (bin > b1) ? vv[j] : 0.0f;
                if (bin == b1) {
                    uint32_t pos = atomicAdd(&s.cand_count, 1u);
                    if (pos < CAND_CAP) { s.cand[pos] = uu[j]; s.cidx[pos] = (uint16_t)(i * 4 + j); }
                }
            }
            float4 o; o.x = ov[0]; o.y = ov[1]; o.z = ov[2]; o.w = ov[3];
            outp[i] = o;
        }
        __syncthreads();

        const uint32_t cc2 = s.cand_count;
        const bool use_cand = (cc2 <= CAND_CAP);
        const int nitems = use_cand ? (int)cc2 : DCOLS;
        const int niterB = (nitems + NT - 1) / NT;

        {
            uint4* h4 = reinterpret_cast<uint4*>(s.hist);
            h4[tid] = make_uint4(0, 0, 0, 0);
        }
        __syncthreads();
        #pragma unroll 1
        for (int it = 0; it < niterB; it++) {
            int i = tid + it * NT;
            bool valid = i < nitems;
            uint32_t u = 0;
            if (valid) u = use_cand ? s.cand[i] : f2u(rowf[i]);
            valid = valid && (use_cand || ((u >> 21) == b1));
            hist_add(s.hist, (u >> 10) & 0x7FFu, valid);
        }
        __syncthreads();
        if (tid < 32) select_from_top(s.hist, NBINS, kk1, &s.bB, &s.kkB, &s.cntC);
        __syncthreads();
        const uint32_t b2 = s.bB;
        const uint32_t kk2 = s.kkB;
        const uint32_t pref22 = (b1 << 11) | b2;

        for (int i = tid; i < 1024; i += NT) s.hist[i] = 0;
        __syncthreads();
        #pragma unroll 1
        for (int it = 0; it < niterB; it++) {
            int i = tid + it * NT;
            bool valid = i < nitems;
            uint32_t u = 0;
            if (valid) u = use_cand ? s.cand[i] : f2u(rowf[i]);
            valid = valid && ((u >> 10) == pref22);
            hist_add(s.hist, u & 0x3FFu, valid);
        }
        __syncthreads();
        if (tid < 32) select_from_top(s.hist, 1024, kk2, &s.bC, &s.kkC, &s.cntC);
        __syncthreads();

        const uint32_t u_t = (b1 << 21) | (b2 << 10) | s.bC;
        const uint32_t A = s.kkC;
        const uint32_t T = s.cntC;
        const bool keep_all_ties = (A == T);

        if (use_cand) {
            for (uint32_t q = tid; q < cc2; q += NT) {
                uint32_t u = s.cand[q];
                bool keep = (u > u_t);
                if (!keep && u == u_t) {
                    if (keep_all_ties) keep = true;
                    else {
                        uint32_t rank = 0;
                        for (uint32_t p = 0; p < cc2; p++)
                            rank += (s.cand[p] == u_t && s.cidx[p] < s.cidx[q]);
                        keep = (rank < A);
                    }
                }
                if (keep) outf[s.cidx[q]] = u2f(u);
            }
        } else {
            for (int i = tid; i < DCOLS; i += NT) {
                uint32_t u = f2u(rowf[i]);
                if ((u >> 21) != b1) continue;
                bool keep = (u > u_t);
                if (!keep && u == u_t) {
                    if (keep_all_ties) keep = true;
                    else {
                        uint32_t rank = 0;
                        for (int q = 0; q < i; q++) rank += (f2u(rowf[q]) == u_t);
                        keep = (rank < A);
                    }
                }
                if (keep) outf[i] = u2f(u);
            }
        }
        return;
    }

    // ===== FAST PATH: exact k-th among candidates, then zero the losers =====
    const int niterC = ((int)ccount + NT - 1) / NT;

    #pragma unroll 1
    for (int it = 0; it < niterC; it++) {
        int i = tid + it * NT;
        bool valid = i < (int)ccount;
        uint32_t u = valid ? s.cand[i] : 0;
        hist_add(s.hist, u >> 21, valid);
    }
    __syncthreads();
    if (tid < 32) select_from_top(s.hist, NBINS, KKEEP, &s.bA, &s.kkA, &s.cntC);
    __syncthreads();
    const uint32_t b1 = s.bA;
    const uint32_t kk1 = s.kkA;

    {
        uint4* h4 = reinterpret_cast<uint4*>(s.hist);
        h4[tid] = make_uint4(0, 0, 0, 0);
    }
    __syncthreads();
    #pragma unroll 1
    for (int it = 0; it < niterC; it++) {
        int i = tid + it * NT;
        bool valid = i < (int)ccount;
        uint32_t u = valid ? s.cand[i] : 0;
        valid = valid && ((u >> 21) == b1);
        hist_add(s.hist, (u >> 10) & 0x7FFu, valid);
    }
    __syncthreads();
    if (tid < 32) select_from_top(s.hist, NBINS, kk1, &s.bB, &s.kkB, &s.cntC);
    __syncthreads();
    const uint32_t b2 = s.bB;
    const uint32_t kk2 = s.kkB;
    const uint32_t pref22 = (b1 << 11) | b2;

    for (int i = tid; i < 1024; i += NT) s.hist[i] = 0;
    __syncthreads();
    #pragma unroll 1
    for (int it = 0; it < niterC; it++) {
        int i = tid + it * NT;
        bool valid = i < (int)ccount;
        uint32_t u = valid ? s.cand[i] : 0;
        valid = valid && ((u >> 10) == pref22);
        hist_add(s.hist, u & 0x3FFu, valid);
    }
    __syncthreads();
    if (tid < 32) select_from_top(s.hist, 1024, kk2, &s.bC, &s.kkC, &s.cntC);
    __syncthreads();

    const uint32_t u_t = (b1 << 21) | (b2 << 10) | s.bC;  // exact k-th largest key
    const uint32_t A = s.kkC;
    const uint32_t T = s.cntC;
    const bool keep_all_ties = (A == T);

    // ---- fixup: zero losers (output already holds v for all candidates) ----
    for (uint32_t q = tid; q < ccount; q += NT) {
        uint32_t u = s.cand[q];
        bool lose = (u < u_t);
        if (!lose && u == u_t && !keep_all_ties) {
            uint32_t rank = 0;
            for (uint32_t p = 0; p < ccount; p++)
                rank += (s.cand[p] == u_t && s.cidx[p] < s.cidx[q]);
            lose = (rank >= A);
        }
        if (lose) outf[s.cidx[q]] = 0.0f;
    }
}

extern "C" void kernel_launch(void* const* d_in, const int* in_sizes, int n_in,
                              void* d_out, int out_size) {
    const float* in = (const float*)d_in[0];
    float* out = (float*)d_out;
    int rows = in_sizes[0] / DCOLS;   // 4096
    wta_kernel<<<rows, NT>>>(in, out, rows);
}